// round 9
// baseline (speedup 1.0000x reference)
#include <cuda_runtime.h>
#include <cstdint>
#include <math.h>

#define BB 4
#define TT 2048
#define DD 1024
#define MTOT (BB * TT)
#define SCALE (0.03125f)

// ---------------- scratch (no allocations allowed) ----------------
__device__ float g_xr[(size_t)MTOT * DD];      // x rounded to tf32
__device__ float g_wr[(size_t)3 * DD * DD];    // W rounded: [k][n]
__device__ float g_q[(size_t)MTOT * DD];       // tf32-rounded
__device__ float g_k[(size_t)MTOT * DD];       // tf32-rounded
__device__ float g_v[(size_t)MTOT * DD];       // tf32-rounded
__device__ float g_kt[(size_t)BB * DD * TT];   // K^T per batch [e][t]
__device__ float g_s[(size_t)BB * TT * TT];    // scores -> att (att tf32-rounded)

// ---------------- helpers ----------------
__device__ __forceinline__ uint32_t f2tf(float x) {
    uint32_t u;
    asm("cvt.rna.tf32.f32 %0, %1;" : "=r"(u) : "f"(x));
    return u;
}
__device__ __forceinline__ float roundtf(float x) {
    return __uint_as_float(f2tf(x));
}
__device__ __forceinline__ void mma_tf32(float* c, const uint32_t* a, const uint32_t* b) {
    asm volatile(
        "mma.sync.aligned.m16n8k8.row.col.f32.tf32.tf32.f32 "
        "{%0,%1,%2,%3}, {%4,%5,%6,%7}, {%8,%9}, {%0,%1,%2,%3};"
        : "+f"(c[0]), "+f"(c[1]), "+f"(c[2]), "+f"(c[3])
        : "r"(a[0]), "r"(a[1]), "r"(a[2]), "r"(a[3]), "r"(b[0]), "r"(b[1]));
}
__device__ __forceinline__ uint32_t smem_u32(const void* p) {
    uint32_t a;
    asm("{ .reg .u64 t; cvta.to.shared.u64 t, %1; cvt.u32.u64 %0, t; }" : "=r"(a) : "l"(p));
    return a;
}
__device__ __forceinline__ void cpa16(uint32_t* dst, const float* src) {
    asm volatile("cp.async.cg.shared.global [%0], [%1], 16;"
                 :: "r"(smem_u32(dst)), "l"(src));
}
#define CP_COMMIT() asm volatile("cp.async.commit_group;" ::: "memory")
#define CP_WAIT1()  asm volatile("cp.async.wait_group 1;" ::: "memory")

// KC=32 chunks, 3 stages.
// A tile [128 m][32 k], row stride 36: frag banks (4g + t) mod 32 all distinct.
// B tile [32 k][128 n], row stride 136: frag banks (8t + g) mod 32 all distinct.
#define KC 32
#define STAGES 3
#define SA 36
#define SB 136
#define A_WORDS (128 * SA)                 // 4608
#define B_WORDS (KC * SB)                  // 4352
#define STAGE_WORDS (A_WORDS + B_WORDS)    // 8960
#define SMEM_BYTES (STAGES * STAGE_WORDS * 4)  // 107520

// ---------------------------------------------------------------------------
// 128x128 block GEMM via tf32 mma.sync + cp.async 3-stage pipeline, KC=32.
//   A: [128, K] row-major (lda).  B: [K, 128] row-major (ldb).
//   Inputs PRE-ROUNDED to tf32 (raw-bit feed).
//   C: [128,128] row-major (ldc), scaled; optional tf32 round on store.
// 256 threads, warps 4(M) x 2(N), warp tile 32x64.  K multiple of 32.
// ---------------------------------------------------------------------------
__device__ __forceinline__ void gemm128_cp(
    const float* __restrict__ A, int lda,
    const float* __restrict__ B, int ldb,
    float* __restrict__ C, int ldc,
    int K, float scale, bool round_out)
{
    extern __shared__ uint32_t dsm[];

    const int tid = threadIdx.x;
    const int wid = tid >> 5, lane = tid & 31;
    const int g = lane >> 2, t = lane & 3;
    const int wm = wid & 3;
    const int wn = wid >> 2;

    // cp.async mappings (per chunk: A 128x32 words, B 32x128 words)
    const int rowA = tid >> 1;            // 0..127
    const int kqA = (tid & 1) * 16;       // word base 0 or 16; 4 float4 each
    const int rowB = tid >> 5;            // 0..7 (rows +8r)
    const int nqB = (tid & 31) * 4;

    float acc[2][8][4];
#pragma unroll
    for (int mi = 0; mi < 2; mi++)
#pragma unroll
        for (int ni = 0; ni < 8; ni++)
#pragma unroll
            for (int j = 0; j < 4; j++) acc[mi][ni][j] = 0.f;

    const int nc = K >> 5;

    auto issue = [&](int c) {
        const int k0 = c * KC;
        uint32_t* st = dsm + (c % STAGES) * STAGE_WORDS;
        const float* Ap = A + (size_t)rowA * lda + k0 + kqA;
        uint32_t* ad = st + rowA * SA + kqA;
#pragma unroll
        for (int j = 0; j < 4; j++)
            cpa16(ad + 4 * j, Ap + 4 * j);
        uint32_t* bt = st + A_WORDS;
#pragma unroll
        for (int r = 0; r < 4; r++)
            cpa16(bt + (rowB + 8 * r) * SB + nqB,
                  B + (size_t)(k0 + rowB + 8 * r) * ldb + nqB);
    };

    issue(0); CP_COMMIT();
    issue(1); CP_COMMIT();

    for (int c = 0; c < nc; c++) {
        CP_WAIT1();
        __syncthreads();
        const uint32_t* As = dsm + (c % STAGES) * STAGE_WORDS;
        const uint32_t* Bs = As + A_WORDS;

#pragma unroll
        for (int ks = 0; ks < KC; ks += 8) {
            uint32_t af[2][4];
#pragma unroll
            for (int mi = 0; mi < 2; mi++) {
                const int r = wm * 32 + mi * 16 + g;
                af[mi][0] = As[r * SA + ks + t];
                af[mi][1] = As[(r + 8) * SA + ks + t];
                af[mi][2] = As[r * SA + ks + t + 4];
                af[mi][3] = As[(r + 8) * SA + ks + t + 4];
            }
            uint32_t bf[8][2];
#pragma unroll
            for (int ni = 0; ni < 8; ni++) {
                const int cc = wn * 64 + ni * 8 + g;
                bf[ni][0] = Bs[(ks + t) * SB + cc];
                bf[ni][1] = Bs[(ks + t + 4) * SB + cc];
            }
#pragma unroll
            for (int mi = 0; mi < 2; mi++)
#pragma unroll
                for (int ni = 0; ni < 8; ni++)
                    mma_tf32(acc[mi][ni], af[mi], bf[ni]);
        }

        if (c + 2 < nc) issue(c + 2);
        CP_COMMIT();
    }

#pragma unroll
    for (int mi = 0; mi < 2; mi++) {
        const int r0 = wm * 32 + mi * 16 + g;
#pragma unroll
        for (int ni = 0; ni < 8; ni++) {
            const int col = wn * 64 + ni * 8 + 2 * t;
            float2 v0, v1;
            if (round_out) {
                v0.x = roundtf(acc[mi][ni][0] * scale); v0.y = roundtf(acc[mi][ni][1] * scale);
                v1.x = roundtf(acc[mi][ni][2] * scale); v1.y = roundtf(acc[mi][ni][3] * scale);
            } else {
                v0.x = acc[mi][ni][0] * scale; v0.y = acc[mi][ni][1] * scale;
                v1.x = acc[mi][ni][2] * scale; v1.y = acc[mi][ni][3] * scale;
            }
            *reinterpret_cast<float2*>(C + (size_t)r0 * ldc + col) = v0;
            *reinterpret_cast<float2*>(C + (size_t)(r0 + 8) * ldc + col) = v1;
        }
    }
}

// ---------------------------------------------------------------------------
// GEMM wrappers (scratch symbols referenced from device code only)
// ---------------------------------------------------------------------------
__global__ void __launch_bounds__(256, 2)
proj_mma()
{
    const int z = blockIdx.z;
    const float* W = g_wr + (size_t)z * DD * DD;
    float* C = ((z == 0) ? g_q : (z == 1) ? g_k : g_v)
             + (size_t)blockIdx.y * 128 * DD + blockIdx.x * 128;
    const float* A = g_xr + (size_t)blockIdx.y * 128 * DD;
    gemm128_cp(A, DD, W + blockIdx.x * 128, DD, C, DD, DD, 1.0f, true);
}

__global__ void __launch_bounds__(256, 2)
scores_mma()
{
    if (blockIdx.x > blockIdx.y) return;   // fully masked tile
    const int b = blockIdx.z;
    const size_t qb = (size_t)blockIdx.y * 128, kb = (size_t)blockIdx.x * 128;
    const float* A = g_q + (size_t)b * TT * DD + qb * DD;     // [q][e]
    const float* B = g_kt + (size_t)b * DD * TT + kb;         // [e][t]
    float* C = g_s + (size_t)b * TT * TT + qb * TT + kb;
    gemm128_cp(A, DD, B, TT, C, TT, DD, SCALE, false);
}

__global__ void __launch_bounds__(256, 2)
pv_mma(float* __restrict__ out)
{
    const int b = blockIdx.z;
    const size_t qb = (size_t)blockIdx.y * 128, eb = (size_t)blockIdx.x * 128;
    const int kmax = (blockIdx.y + 1) * 128;  // att[q,k]=0 beyond q
    const float* A = g_s + (size_t)b * TT * TT + qb * TT;     // [q][t]
    const float* B = g_v + (size_t)b * TT * DD + eb;          // [t][e]
    float* C = out + (size_t)b * TT * DD + qb * DD + eb;
    gemm128_cp(A, TT, B, DD, C, DD, kmax, 1.0f, false);
}

// ---------------------------------------------------------------------------
// Merged tf32 pre-rounding: blocks [0, XB) round x; [XB, XB+3*WB) round W.
// ---------------------------------------------------------------------------
#define XB (MTOT * DD / 4 / 256)   // 8192 blocks
#define WBK (DD * DD / 4 / 256)    // 1024 blocks per W
__global__ void __launch_bounds__(256)
round_all_kernel(const float4* __restrict__ x,
                 const float4* __restrict__ Wq, const float4* __restrict__ Wk,
                 const float4* __restrict__ Wv)
{
    const int bi = blockIdx.x;
    if (bi < XB) {
        const int i = bi * 256 + threadIdx.x;
        float4 v = x[i];
        v.x = roundtf(v.x); v.y = roundtf(v.y);
        v.z = roundtf(v.z); v.w = roundtf(v.w);
        reinterpret_cast<float4*>(g_xr)[i] = v;
    } else {
        const int r = bi - XB;
        const int z = r / WBK;
        const int i = (r % WBK) * 256 + threadIdx.x;
        const float4* src = (z == 0) ? Wq : (z == 1) ? Wk : Wv;
        float4 v = src[i];
        v.x = roundtf(v.x); v.y = roundtf(v.y);
        v.z = roundtf(v.z); v.w = roundtf(v.w);
        reinterpret_cast<float4*>(g_wr)[(size_t)z * (DD * DD / 4) + i] = v;
    }
}

// ---------------------------------------------------------------------------
// K transpose per batch (float4 both directions): g_k [t][e] -> g_kt [e][t]
// ---------------------------------------------------------------------------
__global__ void __launch_bounds__(256)
transpose_k_kernel()
{
    __shared__ float tbuf[64][65];
    const int b = blockIdx.z;
    const float* Km = g_k + (size_t)b * TT * DD;
    float* KT = g_kt + (size_t)b * DD * TT;
    const int tb = blockIdx.x * 64, eb = blockIdx.y * 64;
    const int c4 = threadIdx.x & 15;
    const int r0 = threadIdx.x >> 4;

#pragma unroll
    for (int j = 0; j < 4; j++) {
        const int r = r0 + j * 16;
        float4 v = *reinterpret_cast<const float4*>(
            &Km[(size_t)(tb + r) * DD + eb + c4 * 4]);
        tbuf[r][c4 * 4 + 0] = v.x;
        tbuf[r][c4 * 4 + 1] = v.y;
        tbuf[r][c4 * 4 + 2] = v.z;
        tbuf[r][c4 * 4 + 3] = v.w;
    }
    __syncthreads();
#pragma unroll
    for (int j = 0; j < 4; j++) {
        const int er = r0 + j * 16;
        float4 v;
        v.x = tbuf[c4 * 4 + 0][er];
        v.y = tbuf[c4 * 4 + 1][er];
        v.z = tbuf[c4 * 4 + 2][er];
        v.w = tbuf[c4 * 4 + 3][er];
        *reinterpret_cast<float4*>(&KT[(size_t)(eb + er) * TT + tb + c4 * 4]) = v;
    }
}

// ---------------------------------------------------------------------------
// Causal softmax, float4 path (in-place on g_s); zero-fills k > q; rounds att.
// ---------------------------------------------------------------------------
__global__ void __launch_bounds__(256)
softmax_kernel()
{
    const int row = blockIdx.x;  // b*TT + q
    const int q = row % TT;
    const int n = q + 1;
    float4* s4 = reinterpret_cast<float4*>(g_s + (size_t)row * TT);
    const int tid = threadIdx.x;
    __shared__ float red[256];

    float4 v[2];
    float m = -INFINITY;
#pragma unroll
    for (int i = 0; i < 2; i++) {
        const int idx4 = tid + i * 256;
        v[i] = s4[idx4];
        float* pv = reinterpret_cast<float*>(&v[i]);
        const int base = idx4 * 4;
#pragma unroll
        for (int j = 0; j < 4; j++) {
            if (base + j >= n) pv[j] = -INFINITY;
            else m = fmaxf(m, pv[j]);
        }
    }
    red[tid] = m;
    __syncthreads();
    for (int off = 128; off > 0; off >>= 1) {
        if (tid < off) red[tid] = fmaxf(red[tid], red[tid + off]);
        __syncthreads();
    }
    m = red[0];
    __syncthreads();

    float sum = 0.f;
#pragma unroll
    for (int i = 0; i < 2; i++) {
        float* pv = reinterpret_cast<float*>(&v[i]);
        const int base = (tid + i * 256) * 4;
#pragma unroll
        for (int j = 0; j < 4; j++) {
            const float e = (base + j < n) ? __expf(pv[j] - m) : 0.f;
            pv[j] = e;
            sum += e;
        }
    }
    red[tid] = sum;
    __syncthreads();
    for (int off = 128; off > 0; off >>= 1) {
        if (tid < off) red[tid] += red[tid + off];
        __syncthreads();
    }
    const float inv = 1.f / red[0];
#pragma unroll
    for (int i = 0; i < 2; i++) {
        float* pv = reinterpret_cast<float*>(&v[i]);
        float4 o;
        o.x = roundtf(pv[0] * inv);
        o.y = roundtf(pv[1] * inv);
        o.z = roundtf(pv[2] * inv);
        o.w = roundtf(pv[3] * inv);
        s4[tid + i * 256] = o;
    }
}

// ---------------------------------------------------------------------------
extern "C" void kernel_launch(void* const* d_in, const int* in_sizes, int n_in,
                              void* d_out, int out_size)
{
    const float* x  = (const float*)d_in[0];
    const float* Wq = (const float*)d_in[1];
    const float* Wk = (const float*)d_in[2];
    const float* Wv = (const float*)d_in[3];
    float* out = (float*)d_out;

    cudaFuncSetAttribute(proj_mma,   cudaFuncAttributeMaxDynamicSharedMemorySize, SMEM_BYTES);
    cudaFuncSetAttribute(scores_mma, cudaFuncAttributeMaxDynamicSharedMemorySize, SMEM_BYTES);
    cudaFuncSetAttribute(pv_mma,     cudaFuncAttributeMaxDynamicSharedMemorySize, SMEM_BYTES);

    // 0) pre-round x and W to tf32 (single merged launch)
    round_all_kernel<<<XB + 3 * WBK, 256>>>((const float4*)x, (const float4*)Wq,
                                            (const float4*)Wk, (const float4*)Wv);
    {   // 1) QKV projections (epilogue rounds Q/K/V to tf32)
        dim3 grid(DD / 128, MTOT / 128, 3);
        proj_mma<<<grid, 256, SMEM_BYTES>>>();
    }
    {   // 2) K^T (float4 tiles)
        dim3 grid(TT / 64, DD / 64, BB);
        transpose_k_kernel<<<grid, 256>>>();
    }
    {   // 3) scores = scale * Q K^T (causal block skip)
        dim3 grid(TT / 128, TT / 128, BB);
        scores_mma<<<grid, 256, SMEM_BYTES>>>();
    }
    // 4) softmax (float4, rounds att to tf32)
    softmax_kernel<<<MTOT, 256>>>();
    {   // 5) out = att V
        dim3 grid(DD / 128, TT / 128, BB);
        pv_mma<<<grid, 256, SMEM_BYTES>>>(out);
    }
}

// round 10
// speedup vs baseline: 1.1607x; 1.1607x over previous
#include <cuda_runtime.h>
#include <cstdint>
#include <math.h>

#define BB 4
#define TT 2048
#define DD 1024
#define MTOT (BB * TT)
#define SCALE (0.03125f)

// ---------------- scratch (no allocations allowed) ----------------
// Packed-fragment operands for proj:
__device__ float g_xpk[(size_t)MTOT * DD];     // x, A-fragment-packed, tf32
__device__ float g_wpk[(size_t)3 * DD * DD];   // W, B-fragment-packed, tf32
// Row-major tensors for scores/pv (unchanged R8 pipeline):
__device__ float g_q[(size_t)MTOT * DD];       // tf32-rounded
__device__ float g_k[(size_t)MTOT * DD];       // tf32-rounded
__device__ float g_v[(size_t)MTOT * DD];       // tf32-rounded
__device__ float g_kt[(size_t)BB * DD * TT];   // K^T per batch [e][t]
__device__ float g_s[(size_t)BB * TT * TT];    // scores -> att (att tf32-rounded)

// ---------------- helpers ----------------
__device__ __forceinline__ uint32_t f2tf(float x) {
    uint32_t u;
    asm("cvt.rna.tf32.f32 %0, %1;" : "=r"(u) : "f"(x));
    return u;
}
__device__ __forceinline__ float roundtf(float x) {
    return __uint_as_float(f2tf(x));
}
__device__ __forceinline__ void mma_tf32(float* c, const uint32_t* a, const uint32_t* b) {
    asm volatile(
        "mma.sync.aligned.m16n8k8.row.col.f32.tf32.tf32.f32 "
        "{%0,%1,%2,%3}, {%4,%5,%6,%7}, {%8,%9}, {%0,%1,%2,%3};"
        : "+f"(c[0]), "+f"(c[1]), "+f"(c[2]), "+f"(c[3])
        : "r"(a[0]), "r"(a[1]), "r"(a[2]), "r"(a[3]), "r"(b[0]), "r"(b[1]));
}
__device__ __forceinline__ uint32_t smem_u32(const void* p) {
    uint32_t a;
    asm("{ .reg .u64 t; cvta.to.shared.u64 t, %1; cvt.u32.u64 %0, t; }" : "=r"(a) : "l"(p));
    return a;
}
__device__ __forceinline__ void cpa16(uint32_t* dst, const float* src) {
    asm volatile("cp.async.cg.shared.global [%0], [%1], 16;"
                 :: "r"(smem_u32(dst)), "l"(src));
}
#define CP_COMMIT() asm volatile("cp.async.commit_group;" ::: "memory")
#define CP_WAIT1()  asm volatile("cp.async.wait_group 1;" ::: "memory")

// =====================  classic GEMM (R8 winner, unchanged)  ================
#define KC 16
#define STAGES 3
#define SA 20
#define SB 136
#define A_WORDS (128 * SA)
#define B_WORDS (KC * SB)
#define STAGE_WORDS (A_WORDS + B_WORDS)
#define SMEM_BYTES (STAGES * STAGE_WORDS * 4)   // 56832

__device__ __forceinline__ void gemm128_cp(
    const float* __restrict__ A, int lda,
    const float* __restrict__ B, int ldb,
    float* __restrict__ C, int ldc,
    int K, float scale, bool round_out)
{
    extern __shared__ uint32_t dsm[];

    const int tid = threadIdx.x;
    const int wid = tid >> 5, lane = tid & 31;
    const int g = lane >> 2, t = lane & 3;
    const int wm = wid & 3;
    const int wn = wid >> 2;

    const int rowA = tid >> 2;
    const int kqA = (tid & 3) * 4;
    const int rowB = tid >> 5;
    const int nqB = (tid & 31) * 4;

    float acc[2][8][4];
#pragma unroll
    for (int mi = 0; mi < 2; mi++)
#pragma unroll
        for (int ni = 0; ni < 8; ni++)
#pragma unroll
            for (int j = 0; j < 4; j++) acc[mi][ni][j] = 0.f;

    const int nc = K >> 4;

    auto issue = [&](int c) {
        const int k0 = c * KC;
        uint32_t* st = dsm + (c % STAGES) * STAGE_WORDS;
        cpa16(st + rowA * SA + kqA, A + (size_t)rowA * lda + k0 + kqA);
        cpa16(st + (rowA + 64) * SA + kqA, A + (size_t)(rowA + 64) * lda + k0 + kqA);
        uint32_t* bt = st + A_WORDS;
        cpa16(bt + rowB * SB + nqB, B + (size_t)(k0 + rowB) * ldb + nqB);
        cpa16(bt + (rowB + 8) * SB + nqB, B + (size_t)(k0 + rowB + 8) * ldb + nqB);
    };

    issue(0); CP_COMMIT();
    issue(1); CP_COMMIT();

    for (int c = 0; c < nc; c++) {
        CP_WAIT1();
        __syncthreads();
        const uint32_t* As = dsm + (c % STAGES) * STAGE_WORDS;
        const uint32_t* Bs = As + A_WORDS;

#pragma unroll
        for (int ks = 0; ks < KC; ks += 8) {
            uint32_t af[2][4];
#pragma unroll
            for (int mi = 0; mi < 2; mi++) {
                const int r = wm * 32 + mi * 16 + g;
                af[mi][0] = As[r * SA + ks + t];
                af[mi][1] = As[(r + 8) * SA + ks + t];
                af[mi][2] = As[r * SA + ks + t + 4];
                af[mi][3] = As[(r + 8) * SA + ks + t + 4];
            }
            uint32_t bf[8][2];
#pragma unroll
            for (int ni = 0; ni < 8; ni++) {
                const int cc = wn * 64 + ni * 8 + g;
                bf[ni][0] = Bs[(ks + t) * SB + cc];
                bf[ni][1] = Bs[(ks + t + 4) * SB + cc];
            }
#pragma unroll
            for (int mi = 0; mi < 2; mi++)
#pragma unroll
                for (int ni = 0; ni < 8; ni++)
                    mma_tf32(acc[mi][ni], af[mi], bf[ni]);
        }

        if (c + 2 < nc) issue(c + 2);
        CP_COMMIT();
    }

#pragma unroll
    for (int mi = 0; mi < 2; mi++) {
        const int r0 = wm * 32 + mi * 16 + g;
#pragma unroll
        for (int ni = 0; ni < 8; ni++) {
            const int col = wn * 64 + ni * 8 + 2 * t;
            float2 v0, v1;
            if (round_out) {
                v0.x = roundtf(acc[mi][ni][0] * scale); v0.y = roundtf(acc[mi][ni][1] * scale);
                v1.x = roundtf(acc[mi][ni][2] * scale); v1.y = roundtf(acc[mi][ni][3] * scale);
            } else {
                v0.x = acc[mi][ni][0] * scale; v0.y = acc[mi][ni][1] * scale;
                v1.x = acc[mi][ni][2] * scale; v1.y = acc[mi][ni][3] * scale;
            }
            *reinterpret_cast<float2*>(C + (size_t)r0 * ldc + col) = v0;
            *reinterpret_cast<float2*>(C + (size_t)(r0 + 8) * ldc + col) = v1;
        }
    }
}

// ====================  packed-fragment GEMM (proj only)  ====================
// Packed layouts (K=1024, 64 chunks of 16):
//   A: [m/128 panel][k/16 chunk]{ [k8 slab 0|1][ (m%128)/16 ][128 words] }
//      block word = lane*4+j; lane=(m%8)*4+(k%4); words = a0(g,t) a1(g+8,t)
//      a2(g,t+4) a3(g+8,t+4).
//   B: [n/128 panel][k/16 chunk]{ [k8 slab][ (n%128)/16 ][128 words] }
//      per lane float4 = {b0(n g),b1(n g),b0(n g+8),b1(n g+8)}, b0=(k t), b1=(k t+4).
// One (panel, chunk) slab = 2048 words, linear -> trivial cp.async.
#define PK_CHUNK 2048
#define PK_PANEL (64 * PK_CHUNK)            // 131072 words per 128-panel
#define PSTAGE_WORDS (2 * PK_CHUNK)         // 4096
#define PSMEM_BYTES (STAGES * PSTAGE_WORDS * 4)  // 49152

__global__ void __launch_bounds__(256, 2)
proj_mma_pk()
{
    extern __shared__ uint32_t dsm[];
    const int z = blockIdx.z;
    const float* Apk = g_xpk + (size_t)blockIdx.y * PK_PANEL;
    const float* Bpk = g_wpk + (size_t)z * (8 * PK_PANEL) + (size_t)blockIdx.x * PK_PANEL;
    float* C = ((z == 0) ? g_q : (z == 1) ? g_k : g_v)
             + (size_t)blockIdx.y * 128 * DD + blockIdx.x * 128;

    const int tid = threadIdx.x;
    const int wid = tid >> 5, lane = tid & 31;
    const int g = lane >> 2, t = lane & 3;
    const int wm = wid & 3;
    const int wn = wid >> 2;

    float acc[2][8][4];
#pragma unroll
    for (int mi = 0; mi < 2; mi++)
#pragma unroll
        for (int ni = 0; ni < 8; ni++)
#pragma unroll
            for (int j = 0; j < 4; j++) acc[mi][ni][j] = 0.f;

    auto issue = [&](int c) {
        uint32_t* st = dsm + (c % STAGES) * PSTAGE_WORDS;
        const float* ap = Apk + (size_t)c * PK_CHUNK + tid * 4;
        cpa16(st + tid * 4, ap);
        cpa16(st + tid * 4 + 1024, ap + 1024);
        const float* bp = Bpk + (size_t)c * PK_CHUNK + tid * 4;
        cpa16(st + PK_CHUNK + tid * 4, bp);
        cpa16(st + PK_CHUNK + tid * 4 + 1024, bp + 1024);
    };

    issue(0); CP_COMMIT();
    issue(1); CP_COMMIT();

    const int nc = DD / KC;  // 64
    for (int c = 0; c < nc; c++) {
        CP_WAIT1();
        __syncthreads();
        const uint32_t* As = dsm + (c % STAGES) * PSTAGE_WORDS;
        const uint32_t* Bs = As + PK_CHUNK;

#pragma unroll
        for (int s = 0; s < 2; s++) {       // k8 slabs (ks = 0, 8)
            uint4 af[2], bq[4];
#pragma unroll
            for (int mi = 0; mi < 2; mi++)
                af[mi] = *reinterpret_cast<const uint4*>(
                    As + s * 1024 + (wm * 2 + mi) * 128 + lane * 4);
#pragma unroll
            for (int p = 0; p < 4; p++)
                bq[p] = *reinterpret_cast<const uint4*>(
                    Bs + s * 1024 + (wn * 4 + p) * 128 + lane * 4);
#pragma unroll
            for (int mi = 0; mi < 2; mi++)
#pragma unroll
                for (int ni = 0; ni < 8; ni++) {
                    const uint32_t* bp = reinterpret_cast<const uint32_t*>(&bq[ni >> 1])
                                       + (ni & 1) * 2;
                    mma_tf32(acc[mi][ni], reinterpret_cast<const uint32_t*>(&af[mi]), bp);
                }
        }

        if (c + 2 < nc) issue(c + 2);
        CP_COMMIT();
    }

    // epilogue: row-major tf32-rounded stores (Q/K/V consumed row-major)
#pragma unroll
    for (int mi = 0; mi < 2; mi++) {
        const int r0 = wm * 32 + mi * 16 + g;
#pragma unroll
        for (int ni = 0; ni < 8; ni++) {
            const int col = wn * 64 + ni * 8 + 2 * t;
            float2 v0, v1;
            v0.x = roundtf(acc[mi][ni][0]); v0.y = roundtf(acc[mi][ni][1]);
            v1.x = roundtf(acc[mi][ni][2]); v1.y = roundtf(acc[mi][ni][3]);
            *reinterpret_cast<float2*>(C + (size_t)r0 * DD + col) = v0;
            *reinterpret_cast<float2*>(C + (size_t)(r0 + 8) * DD + col) = v1;
        }
    }
}

// ---------------------------------------------------------------------------
// Pre-pack passes (round to tf32 + fragment-pack).  One thread per lane-slot.
// ---------------------------------------------------------------------------
__global__ void __launch_bounds__(256)
pack_x_kernel(const float* __restrict__ x)
{
    const int idx = blockIdx.x * 256 + threadIdx.x;   // 2M threads
    const int lane = idx & 31;
    const int blk = idx >> 5;            // (mb, kb): mb 0..511, kb 0..127
    const int kb = blk & 127;
    const int mb = blk >> 7;
    const int m0 = mb * 16, k0 = kb * 8;
    const int g = lane >> 2, t = lane & 3;

    float4 v;
    v.x = roundtf(x[(size_t)(m0 + g) * DD + k0 + t]);
    v.y = roundtf(x[(size_t)(m0 + g + 8) * DD + k0 + t]);
    v.z = roundtf(x[(size_t)(m0 + g) * DD + k0 + t + 4]);
    v.w = roundtf(x[(size_t)(m0 + g + 8) * DD + k0 + t + 4]);

    const int panel = mb >> 3, mbl = mb & 7, chunk = kb >> 1, slab = kb & 1;
    const size_t off = (size_t)(panel * 64 + chunk) * PK_CHUNK
                     + slab * 1024 + mbl * 128 + lane * 4;
    *reinterpret_cast<float4*>(g_xpk + off) = v;
}

__global__ void __launch_bounds__(256)
pack_w_kernel(const float* __restrict__ Wq, const float* __restrict__ Wk,
              const float* __restrict__ Wv)
{
    const int z = blockIdx.y;
    const float* W = (z == 0) ? Wq : (z == 1) ? Wk : Wv;   // [k][n]
    const int idx = blockIdx.x * 256 + threadIdx.x;        // 256K threads
    const int lane = idx & 31;
    const int blk = idx >> 5;            // (kb, nbp): kb 0..127, nbp 0..63
    const int kb = blk & 127;
    const int nbp = blk >> 7;
    const int k0 = kb * 8, n0 = nbp * 16;
    const int gn = lane >> 2, tk = lane & 3;

    float4 v;
    v.x = roundtf(W[(size_t)(k0 + tk) * DD + n0 + gn]);
    v.y = roundtf(W[(size_t)(k0 + tk + 4) * DD + n0 + gn]);
    v.z = roundtf(W[(size_t)(k0 + tk) * DD + n0 + 8 + gn]);
    v.w = roundtf(W[(size_t)(k0 + tk + 4) * DD + n0 + 8 + gn]);

    const int panel = nbp >> 3, nbl = nbp & 7, chunk = kb >> 1, slab = kb & 1;
    const size_t off = (size_t)z * (8 * PK_PANEL)
                     + (size_t)(panel * 64 + chunk) * PK_CHUNK
                     + slab * 1024 + nbl * 128 + lane * 4;
    *reinterpret_cast<float4*>(g_wpk + off) = v;
}

// ---------------------------------------------------------------------------
// scores / pv wrappers (classic path, unchanged)
// ---------------------------------------------------------------------------
__global__ void __launch_bounds__(256, 2)
scores_mma()
{
    if (blockIdx.x > blockIdx.y) return;
    const int b = blockIdx.z;
    const size_t qb = (size_t)blockIdx.y * 128, kb = (size_t)blockIdx.x * 128;
    const float* A = g_q + (size_t)b * TT * DD + qb * DD;
    const float* B = g_kt + (size_t)b * DD * TT + kb;
    float* C = g_s + (size_t)b * TT * TT + qb * TT + kb;
    gemm128_cp(A, DD, B, TT, C, TT, DD, SCALE, false);
}

__global__ void __launch_bounds__(256, 2)
pv_mma(float* __restrict__ out)
{
    const int b = blockIdx.z;
    const size_t qb = (size_t)blockIdx.y * 128, eb = (size_t)blockIdx.x * 128;
    const int kmax = (blockIdx.y + 1) * 128;
    const float* A = g_s + (size_t)b * TT * TT + qb * TT;
    const float* B = g_v + (size_t)b * TT * DD + eb;
    float* C = out + (size_t)b * TT * DD + qb * DD + eb;
    gemm128_cp(A, TT, B, DD, C, DD, kmax, 1.0f, false);
}

// ---------------------------------------------------------------------------
// K transpose per batch (float4 both directions)
// ---------------------------------------------------------------------------
__global__ void __launch_bounds__(256)
transpose_k_kernel()
{
    __shared__ float tbuf[64][65];
    const int b = blockIdx.z;
    const float* Km = g_k + (size_t)b * TT * DD;
    float* KT = g_kt + (size_t)b * DD * TT;
    const int tb = blockIdx.x * 64, eb = blockIdx.y * 64;
    const int c4 = threadIdx.x & 15;
    const int r0 = threadIdx.x >> 4;

#pragma unroll
    for (int j = 0; j < 4; j++) {
        const int r = r0 + j * 16;
        float4 v = *reinterpret_cast<const float4*>(
            &Km[(size_t)(tb + r) * DD + eb + c4 * 4]);
        tbuf[r][c4 * 4 + 0] = v.x;
        tbuf[r][c4 * 4 + 1] = v.y;
        tbuf[r][c4 * 4 + 2] = v.z;
        tbuf[r][c4 * 4 + 3] = v.w;
    }
    __syncthreads();
#pragma unroll
    for (int j = 0; j < 4; j++) {
        const int er = r0 + j * 16;
        float4 v;
        v.x = tbuf[c4 * 4 + 0][er];
        v.y = tbuf[c4 * 4 + 1][er];
        v.z = tbuf[c4 * 4 + 2][er];
        v.w = tbuf[c4 * 4 + 3][er];
        *reinterpret_cast<float4*>(&KT[(size_t)(eb + er) * TT + tb + c4 * 4]) = v;
    }
}

// ---------------------------------------------------------------------------
// Causal softmax, float4 path (in-place on g_s)
// ---------------------------------------------------------------------------
__global__ void __launch_bounds__(256)
softmax_kernel()
{
    const int row = blockIdx.x;
    const int q = row % TT;
    const int n = q + 1;
    float4* s4 = reinterpret_cast<float4*>(g_s + (size_t)row * TT);
    const int tid = threadIdx.x;
    __shared__ float red[256];

    float4 v[2];
    float m = -INFINITY;
#pragma unroll
    for (int i = 0; i < 2; i++) {
        const int idx4 = tid + i * 256;
        v[i] = s4[idx4];
        float* pv = reinterpret_cast<float*>(&v[i]);
        const int base = idx4 * 4;
#pragma unroll
        for (int j = 0; j < 4; j++) {
            if (base + j >= n) pv[j] = -INFINITY;
            else m = fmaxf(m, pv[j]);
        }
    }
    red[tid] = m;
    __syncthreads();
    for (int off = 128; off > 0; off >>= 1) {
        if (tid < off) red[tid] = fmaxf(red[tid], red[tid + off]);
        __syncthreads();
    }
    m = red[0];
    __syncthreads();

    float sum = 0.f;
#pragma unroll
    for (int i = 0; i < 2; i++) {
        float* pv = reinterpret_cast<float*>(&v[i]);
        const int base = (tid + i * 256) * 4;
#pragma unroll
        for (int j = 0; j < 4; j++) {
            const float e = (base + j < n) ? __expf(pv[j] - m) : 0.f;
            pv[j] = e;
            sum += e;
        }
    }
    red[tid] = sum;
    __syncthreads();
    for (int off = 128; off > 0; off >>= 1) {
        if (tid < off) red[tid] += red[tid + off];
        __syncthreads();
    }
    const float inv = 1.f / red[0];
#pragma unroll
    for (int i = 0; i < 2; i++) {
        float* pv = reinterpret_cast<float*>(&v[i]);
        float4 o;
        o.x = roundtf(pv[0] * inv);
        o.y = roundtf(pv[1] * inv);
        o.z = roundtf(pv[2] * inv);
        o.w = roundtf(pv[3] * inv);
        s4[tid + i * 256] = o;
    }
}

// ---------------------------------------------------------------------------
extern "C" void kernel_launch(void* const* d_in, const int* in_sizes, int n_in,
                              void* d_out, int out_size)
{
    const float* x  = (const float*)d_in[0];
    const float* Wq = (const float*)d_in[1];
    const float* Wk = (const float*)d_in[2];
    const float* Wv = (const float*)d_in[3];
    float* out = (float*)d_out;

    cudaFuncSetAttribute(proj_mma_pk, cudaFuncAttributeMaxDynamicSharedMemorySize, PSMEM_BYTES);
    cudaFuncSetAttribute(scores_mma,  cudaFuncAttributeMaxDynamicSharedMemorySize, SMEM_BYTES);
    cudaFuncSetAttribute(pv_mma,      cudaFuncAttributeMaxDynamicSharedMemorySize, SMEM_BYTES);

    // 0) round+fragment-pack x and W
    pack_x_kernel<<<(MTOT / 16) * (DD / 8) * 32 / 256, 256>>>(x);
    {
        dim3 grid((DD / 8) * (DD / 16) * 32 / 256, 3);
        pack_w_kernel<<<grid, 256>>>(Wq, Wk, Wv);
    }
    {   // 1) QKV projections (packed-fragment tensor path)
        dim3 grid(DD / 128, MTOT / 128, 3);
        proj_mma_pk<<<grid, 256, PSMEM_BYTES>>>();
    }
    {   // 2) K^T
        dim3 grid(TT / 64, DD / 64, BB);
        transpose_k_kernel<<<grid, 256>>>();
    }
    {   // 3) scores = scale * Q K^T (causal block skip)
        dim3 grid(TT / 128, TT / 128, BB);
        scores_mma<<<grid, 256, SMEM_BYTES>>>();
    }
    // 4) softmax
    softmax_kernel<<<MTOT, 256>>>();
    {   // 5) out = att V
        dim3 grid(DD / 128, TT / 128, BB);
        pv_mma<<<grid, 256, SMEM_BYTES>>>(out);
    }
}